// round 7
// baseline (speedup 1.0000x reference)
#include <cuda_runtime.h>
#include <math.h>
#include <stdint.h>

// Problem constants
#define BATCH 8
#define CH    512
#define HW    4096
#define GROUPS 32
#define CPG   16
#define EPS   1e-5f
#define SCALE 0.04419417382415922f   // 512^-0.5

#define STAGES 4
#define SROW   20                     // padded row stride (conflict-free)
#define STAGE_U32 (128 * SROW)        // uint32 per operand per stage
#define SMEM_BYTES (STAGES * STAGE_U32 * 4 * 2)   // 81920 B

// ---------------------------------------------------------------------------
// Scratch (device globals; allocation in kernel_launch is forbidden)
// ---------------------------------------------------------------------------
__device__ float g_t [(long long)BATCH * HW * CH];   // tokens, later attn out
__device__ float g_q [(long long)BATCH * HW * CH];
__device__ float g_k [(long long)BATCH * HW * CH];
__device__ float g_vt[(long long)BATCH * CH * HW];   // V^T (B,C,HW)
__device__ float g_s [(long long)BATCH * HW * HW];   // scores ~537MB

// ---------------------------------------------------------------------------
__device__ __forceinline__ float warpSum(float v) {
#pragma unroll
    for (int o = 16; o > 0; o >>= 1) v += __shfl_xor_sync(0xffffffffu, v, o);
    return v;
}
__device__ __forceinline__ float warpMax(float v) {
#pragma unroll
    for (int o = 16; o > 0; o >>= 1) v = fmaxf(v, __shfl_xor_sync(0xffffffffu, v, o));
    return v;
}
__device__ __forceinline__ void mma8(float* c, const uint32_t* a, const uint32_t* b) {
    asm volatile(
        "mma.sync.aligned.m16n8k8.row.col.f32.tf32.tf32.f32 "
        "{%0,%1,%2,%3},{%4,%5,%6,%7},{%8,%9},{%0,%1,%2,%3};\n"
        : "+f"(c[0]), "+f"(c[1]), "+f"(c[2]), "+f"(c[3])
        : "r"(a[0]), "r"(a[1]), "r"(a[2]), "r"(a[3]), "r"(b[0]), "r"(b[1]));
}
__device__ __forceinline__ void cp16(uint32_t smem_addr, const void* gptr) {
    asm volatile("cp.async.cg.shared.global [%0], [%1], 16;\n"
                 :: "r"(smem_addr), "l"(gptr));
}
__device__ __forceinline__ void cp_commit() {
    asm volatile("cp.async.commit_group;\n" ::: "memory");
}
template<int N>
__device__ __forceinline__ void cp_wait() {
    asm volatile("cp.async.wait_group %0;\n" :: "n"(N) : "memory");
}

// ---------------------------------------------------------------------------
// GroupNorm + transpose to token-major (B,HW,C)
// ---------------------------------------------------------------------------
__global__ void __launch_bounds__(256) groupnorm_kernel(
    const float* __restrict__ x, const float* __restrict__ gamma,
    const float* __restrict__ beta, float* __restrict__ t)
{
    const int bg = blockIdx.x;
    const int b = bg >> 5, g = bg & 31;
    const int tid = threadIdx.x;
    const float* xg = x + ((long long)b * CH + (long long)g * CPG) * HW;

    float s = 0.f, ss = 0.f;
    const float4* x4 = (const float4*)xg;
    const int n4 = CPG * HW / 4;
    for (int i = tid; i < n4; i += 256) {
        float4 v = x4[i];
        s  += v.x + v.y + v.z + v.w;
        ss += v.x*v.x + v.y*v.y + v.z*v.z + v.w*v.w;
    }
    s = warpSum(s); ss = warpSum(ss);
    __shared__ float shs[8], shss[8];
    __shared__ float s_mean, s_rstd;
    const int lane = tid & 31, wid = tid >> 5;
    if (lane == 0) { shs[wid] = s; shss[wid] = ss; }
    __syncthreads();
    if (tid < 32) {
        float a = (lane < 8) ? shs[lane]  : 0.f;
        float c = (lane < 8) ? shss[lane] : 0.f;
        a = warpSum(a); c = warpSum(c);
        if (lane == 0) {
            const float inv_n = 1.f / (float)(CPG * HW);
            float mean = a * inv_n;
            float var  = c * inv_n - mean * mean;
            s_mean = mean;
            s_rstd = rsqrtf(var + EPS);
        }
    }
    __syncthreads();
    const float mean = s_mean, rstd = s_rstd;

    const int cl = tid & 15;
    const int pr = tid >> 4;
    const int c0 = g * CPG;
    const float gm = gamma[c0 + cl] * rstd;
    const float bt = beta[c0 + cl] - mean * gm;

    __shared__ float tile[CPG][257];
    float* tb = t + (long long)b * HW * CH + c0;
    for (int pbase = 0; pbase < HW; pbase += 256) {
#pragma unroll
        for (int c = 0; c < CPG; c++)
            tile[c][tid] = xg[(long long)c * HW + pbase + tid];
        __syncthreads();
#pragma unroll
        for (int pp = 0; pp < 16; pp++) {
            int pl = pp * 16 + pr;
            tb[(long long)(pbase + pl) * CH + cl] = tile[cl][pl] * gm + bt;
        }
        __syncthreads();
    }
}

// ---------------------------------------------------------------------------
// TF32 tensor-core GEMM-NT: C[m][n] = alpha*sum_k A[m][k]*B[n][k] (+bias)(+resid)
// A: MxK row-major, B: NxK row-major, C: MxN row-major.
// 128x128 block tile, K-tile 16, 8 warps (2x4), warp tile 64x32.
// 4-stage cp.async pipeline (dynamic smem 80KB), prefetch distance 3,
// one (possibly empty) commit group per iteration so wait_group<2> always
// drains exactly the stage being consumed.
// BIAS: 0 none, 1 per-col (bias[n]), 2 per-row (bias[m]).
// All dims divide tiles exactly in this problem -> no bounds checks.
// ---------------------------------------------------------------------------
template<int BIAS, bool ADD_RESID>
__global__ void __launch_bounds__(256, 2) mma_nt(
    const float* __restrict__ A, const float* __restrict__ Bm,
    float* __restrict__ C, const float* __restrict__ bias,
    const float* __restrict__ resid,
    int M, int N, int K, float alpha,
    long long sA, long long sB, long long sC, long long sR)
{
    extern __shared__ uint32_t smem[];
    uint32_t* As = smem;                          // [STAGES][128][SROW]
    uint32_t* Bs = smem + STAGES * STAGE_U32;     // [STAGES][128][SROW]

    const int z = blockIdx.z;
    A  += z * sA;
    Bm += z * sB;
    C  += z * sC;
    if (ADD_RESID) resid += z * sR;

    const int bm = blockIdx.y * 128;
    const int bn = blockIdx.x * 128;
    const int tid  = threadIdx.x;
    const int lane = tid & 31;
    const int wid  = tid >> 5;
    const int wm = wid >> 2;          // 0..1
    const int wn = wid & 3;           // 0..3
    const int g  = lane >> 2;         // 0..7
    const int t  = lane & 3;          // 0..3

    // global load coords: 2 16B chunks per operand per thread
    const int r0  = tid >> 2;         // 0..63
    const int r1  = r0 + 64;
    const int col = (tid & 3) << 2;   // 0,4,8,12

    const float* Apl = A  + (long long)(bm + r0) * K + col;
    const float* Aph = A  + (long long)(bm + r1) * K + col;
    const float* Bpl = Bm + (long long)(bn + r0) * K + col;
    const float* Bph = Bm + (long long)(bn + r1) * K + col;

    // per-stage smem destinations
    uint32_t dA0[STAGES], dA1[STAGES], dB0[STAGES], dB1[STAGES];
#pragma unroll
    for (int s2 = 0; s2 < STAGES; s2++) {
        dA0[s2] = (uint32_t)__cvta_generic_to_shared(&As[s2*STAGE_U32 + r0*SROW + col]);
        dA1[s2] = (uint32_t)__cvta_generic_to_shared(&As[s2*STAGE_U32 + r1*SROW + col]);
        dB0[s2] = (uint32_t)__cvta_generic_to_shared(&Bs[s2*STAGE_U32 + r0*SROW + col]);
        dB1[s2] = (uint32_t)__cvta_generic_to_shared(&Bs[s2*STAGE_U32 + r1*SROW + col]);
    }

    float acc[4][4][4];
#pragma unroll
    for (int i = 0; i < 4; i++)
#pragma unroll
        for (int j = 0; j < 4; j++)
#pragma unroll
            for (int e = 0; e < 4; e++) acc[i][j][e] = 0.f;

    const int nt = K >> 4;            // >= 32 for all calls here

    // prologue: issue stages 0..2 (3 groups in flight)
#pragma unroll
    for (int p = 0; p < STAGES - 1; p++) {
        int off = p << 4;
        cp16(dA0[p], Apl + off); cp16(dA1[p], Aph + off);
        cp16(dB0[p], Bpl + off); cp16(dB1[p], Bph + off);
        cp_commit();
    }

    for (int kt = 0; kt < nt; kt++) {
        cp_wait<STAGES - 2>();        // stage kt%STAGES has landed
        __syncthreads();              // all warps done with the stage we refill

        {                             // prefetch kt+3 (possibly empty group)
            int pf = kt + STAGES - 1;
            if (pf < nt) {
                int sb = pf & (STAGES - 1);
                int off = pf << 4;
                cp16(dA0[sb], Apl + off); cp16(dA1[sb], Aph + off);
                cp16(dB0[sb], Bpl + off); cp16(dB1[sb], Bph + off);
            }
            cp_commit();              // always: keeps group accounting exact
        }

        const uint32_t* Abuf = As + (kt & (STAGES - 1)) * STAGE_U32;
        const uint32_t* Bbuf = Bs + (kt & (STAGES - 1)) * STAGE_U32;
#pragma unroll
        for (int ks = 0; ks < 2; ks++) {
            const int kk = ks * 8;
            uint32_t af[4][4], bf[4][2];
#pragma unroll
            for (int mt = 0; mt < 4; mt++) {
                const uint32_t* p = &Abuf[(wm*64 + mt*16 + g)*SROW + kk + t];
                af[mt][0] = p[0];
                af[mt][1] = p[8 * SROW];
                af[mt][2] = p[4];
                af[mt][3] = p[8 * SROW + 4];
            }
#pragma unroll
            for (int jt = 0; jt < 4; jt++) {
                const uint32_t* p = &Bbuf[(wn*32 + jt*8 + g)*SROW + kk + t];
                bf[jt][0] = p[0];
                bf[jt][1] = p[4];
            }
#pragma unroll
            for (int mt = 0; mt < 4; mt++)
#pragma unroll
                for (int jt = 0; jt < 4; jt++)
                    mma8(acc[mt][jt], af[mt], bf[jt]);
        }
    }

    // Epilogue: float2 stores, coalesced row-major
#pragma unroll
    for (int mt = 0; mt < 4; mt++) {
        const int m0 = bm + wm*64 + mt*16 + g;
        const int m1 = m0 + 8;
        float rb0 = 0.f, rb1 = 0.f;
        if (BIAS == 2) { rb0 = bias[m0]; rb1 = bias[m1]; }
#pragma unroll
        for (int jt = 0; jt < 4; jt++) {
            const int n0 = bn + wn*32 + jt*8 + t*2;
            float2 cb = make_float2(0.f, 0.f);
            if (BIAS == 1) cb = *(const float2*)(bias + n0);
            float2 v0, v1;
            v0.x = acc[mt][jt][0]*alpha; v0.y = acc[mt][jt][1]*alpha;
            v1.x = acc[mt][jt][2]*alpha; v1.y = acc[mt][jt][3]*alpha;
            if (BIAS == 1) { v0.x+=cb.x; v0.y+=cb.y; v1.x+=cb.x; v1.y+=cb.y; }
            if (BIAS == 2) { v0.x+=rb0; v0.y+=rb0; v1.x+=rb1; v1.y+=rb1; }
            if (ADD_RESID) {
                float2 r0v = *(const float2*)(resid + (long long)m0 * N + n0);
                float2 r1v = *(const float2*)(resid + (long long)m1 * N + n0);
                v0.x+=r0v.x; v0.y+=r0v.y; v1.x+=r1v.x; v1.y+=r1v.y;
            }
            *(float2*)(C + (long long)m0 * N + n0) = v0;
            *(float2*)(C + (long long)m1 * N + n0) = v1;
        }
    }
}

// ---------------------------------------------------------------------------
// Row softmax over 4096 entries; row lives in registers between passes.
// ---------------------------------------------------------------------------
__global__ void __launch_bounds__(256) softmax_kernel(float* __restrict__ s)
{
    float4* row = (float4*)(s + (long long)blockIdx.x * HW);
    const int tid = threadIdx.x;
    const int lane = tid & 31, wid = tid >> 5;
    __shared__ float sh[8];
    __shared__ float s_bcast;

    float4 v[4];
    float m = -INFINITY;
#pragma unroll
    for (int u = 0; u < 4; u++) {
        v[u] = row[tid + u * 256];
        m = fmaxf(m, fmaxf(fmaxf(v[u].x, v[u].y), fmaxf(v[u].z, v[u].w)));
    }
    m = warpMax(m);
    if (lane == 0) sh[wid] = m;
    __syncthreads();
    if (tid < 32) {
        float a = (lane < 8) ? sh[lane] : -INFINITY;
        a = warpMax(a);
        if (lane == 0) s_bcast = a;
    }
    __syncthreads();
    m = s_bcast;

    float sum = 0.f;
#pragma unroll
    for (int u = 0; u < 4; u++) {
        v[u].x = __expf(v[u].x - m); v[u].y = __expf(v[u].y - m);
        v[u].z = __expf(v[u].z - m); v[u].w = __expf(v[u].w - m);
        sum += v[u].x + v[u].y + v[u].z + v[u].w;
    }
    sum = warpSum(sum);
    __syncthreads();
    if (lane == 0) sh[wid] = sum;
    __syncthreads();
    if (tid < 32) {
        float a = (lane < 8) ? sh[lane] : 0.f;
        a = warpSum(a);
        if (lane == 0) s_bcast = a;
    }
    __syncthreads();
    const float inv = 1.f / s_bcast;
#pragma unroll
    for (int u = 0; u < 4; u++) {
        v[u].x *= inv; v[u].y *= inv; v[u].z *= inv; v[u].w *= inv;
        row[tid + u * 256] = v[u];
    }
}

// ---------------------------------------------------------------------------
// Launch. All GEMMs are NT on tensor cores; transposed outputs realized by
// operand swap (compute W * X^T) instead of scattered epilogues.
// ---------------------------------------------------------------------------
extern "C" void kernel_launch(void* const* d_in, const int* in_sizes, int n_in,
                              void* d_out, int out_size)
{
    const float* x    = (const float*)d_in[0];
    const float* gn_w = (const float*)d_in[1];
    const float* gn_b = (const float*)d_in[2];
    const float* wq   = (const float*)d_in[3];
    const float* bq   = (const float*)d_in[4];
    const float* wk   = (const float*)d_in[5];
    const float* bk   = (const float*)d_in[6];
    const float* wv   = (const float*)d_in[7];
    const float* bv   = (const float*)d_in[8];
    const float* wo   = (const float*)d_in[9];
    const float* bo   = (const float*)d_in[10];
    float* out = (float*)d_out;

    float *t, *q, *k, *vt, *s;
    cudaGetSymbolAddress((void**)&t,  g_t);
    cudaGetSymbolAddress((void**)&q,  g_q);
    cudaGetSymbolAddress((void**)&k,  g_k);
    cudaGetSymbolAddress((void**)&vt, g_vt);
    cudaGetSymbolAddress((void**)&s,  g_s);
    float* o = t;   // tokens dead after V projection; reuse

    const long long sTok = (long long)HW * CH;
    const long long sSc  = (long long)HW * HW;

    // allow 80KB dynamic smem on every instantiation (idempotent, capture-safe)
    cudaFuncSetAttribute(mma_nt<1, false>,
        cudaFuncAttributeMaxDynamicSharedMemorySize, SMEM_BYTES);
    cudaFuncSetAttribute(mma_nt<2, false>,
        cudaFuncAttributeMaxDynamicSharedMemorySize, SMEM_BYTES);
    cudaFuncSetAttribute(mma_nt<0, false>,
        cudaFuncAttributeMaxDynamicSharedMemorySize, SMEM_BYTES);
    cudaFuncSetAttribute(mma_nt<2, true>,
        cudaFuncAttributeMaxDynamicSharedMemorySize, SMEM_BYTES);

    // 1) GroupNorm -> tokens (B,HW,C)
    groupnorm_kernel<<<BATCH * GROUPS, 256>>>(x, gn_w, gn_b, t);

    // 2) Q = t @ Wq^T + bq ; K likewise.  M=HW, N=CH, K=CH, col bias.
    dim3 gQK(CH / 128, HW / 128, BATCH);
    mma_nt<1, false><<<gQK, 256, SMEM_BYTES>>>(t, wq, q, bq, nullptr,
        HW, CH, CH, 1.f, sTok, 0, sTok, 0);
    mma_nt<1, false><<<gQK, 256, SMEM_BYTES>>>(t, wk, k, bk, nullptr,
        HW, CH, CH, 1.f, sTok, 0, sTok, 0);

    // 3) V^T = Wv @ t^T + bv (per-row bias). M=CH, N=HW, K=CH.
    dim3 gVT(HW / 128, CH / 128, BATCH);
    mma_nt<2, false><<<gVT, 256, SMEM_BYTES>>>(wv, t, vt, bv, nullptr,
        CH, HW, CH, 1.f, 0, sTok, sTok, 0);

    // 4) scores = scale * Q @ K^T. M=N=HW, K=CH.
    dim3 gSc(HW / 128, HW / 128, BATCH);
    mma_nt<0, false><<<gSc, 256, SMEM_BYTES>>>(q, k, s, nullptr, nullptr,
        HW, HW, CH, SCALE, sTok, sTok, sSc, 0);

    // 5) softmax rows
    softmax_kernel<<<BATCH * HW, 256>>>(s);

    // 6) O = P @ V  (B = vt rows are channels: NT). M=HW, N=CH, K=HW.
    dim3 gPV(CH / 128, HW / 128, BATCH);
    mma_nt<0, false><<<gPV, 256, SMEM_BYTES>>>(s, vt, o, nullptr, nullptr,
        HW, CH, HW, 1.f, sSc, sTok, sTok, 0);

    // 7) out^T = Wo @ O^T + bo + x, directly in (B,C,HW). M=CH, N=HW, K=CH.
    dim3 gO(HW / 128, CH / 128, BATCH);
    mma_nt<2, true><<<gO, 256, SMEM_BYTES>>>(wo, o, out, bo, x,
        CH, HW, CH, 1.f, 0, sTok, sTok, sTok);
}

// round 8
// speedup vs baseline: 1.0357x; 1.0357x over previous
#include <cuda_runtime.h>
#include <math.h>
#include <stdint.h>

// Problem constants
#define BATCH 8
#define CH    512
#define HW    4096
#define GROUPS 32
#define CPG   16
#define EPS   1e-5f
#define SCALE 0.04419417382415922f   // 512^-0.5

#define STAGES 4
#define SROW   20                     // padded row stride (conflict-free)
#define STAGE_U32 (128 * SROW)        // uint32 per operand per stage
#define SMEM_BYTES (STAGES * STAGE_U32 * 4 * 2)   // 81920 B

// ---------------------------------------------------------------------------
// Scratch (device globals; allocation in kernel_launch is forbidden)
// ---------------------------------------------------------------------------
__device__ float g_t [(long long)BATCH * HW * CH];   // tokens, later attn out
__device__ float g_q [(long long)BATCH * HW * CH];
__device__ float g_k [(long long)BATCH * HW * CH];
__device__ float g_vt[(long long)BATCH * CH * HW];   // V^T (B,C,HW)
__device__ float g_s [(long long)BATCH * HW * HW];   // scores ~537MB

// ---------------------------------------------------------------------------
__device__ __forceinline__ float warpSum(float v) {
#pragma unroll
    for (int o = 16; o > 0; o >>= 1) v += __shfl_xor_sync(0xffffffffu, v, o);
    return v;
}
__device__ __forceinline__ float warpMax(float v) {
#pragma unroll
    for (int o = 16; o > 0; o >>= 1) v = fmaxf(v, __shfl_xor_sync(0xffffffffu, v, o));
    return v;
}
__device__ __forceinline__ void mma8(float* c, const uint32_t* a, const uint32_t* b) {
    asm volatile(
        "mma.sync.aligned.m16n8k8.row.col.f32.tf32.tf32.f32 "
        "{%0,%1,%2,%3},{%4,%5,%6,%7},{%8,%9},{%0,%1,%2,%3};\n"
        : "+f"(c[0]), "+f"(c[1]), "+f"(c[2]), "+f"(c[3])
        : "r"(a[0]), "r"(a[1]), "r"(a[2]), "r"(a[3]), "r"(b[0]), "r"(b[1]));
}
__device__ __forceinline__ void cp16(uint32_t smem_addr, const void* gptr) {
    asm volatile("cp.async.cg.shared.global [%0], [%1], 16;\n"
                 :: "r"(smem_addr), "l"(gptr));
}
__device__ __forceinline__ void cp_commit() {
    asm volatile("cp.async.commit_group;\n" ::: "memory");
}
template<int N>
__device__ __forceinline__ void cp_wait() {
    asm volatile("cp.async.wait_group %0;\n" :: "n"(N) : "memory");
}

// ---------------------------------------------------------------------------
// GroupNorm + transpose to token-major (B,HW,C)
// ---------------------------------------------------------------------------
__global__ void __launch_bounds__(256) groupnorm_kernel(
    const float* __restrict__ x, const float* __restrict__ gamma,
    const float* __restrict__ beta, float* __restrict__ t)
{
    const int bg = blockIdx.x;
    const int b = bg >> 5, g = bg & 31;
    const int tid = threadIdx.x;
    const float* xg = x + ((long long)b * CH + (long long)g * CPG) * HW;

    float s = 0.f, ss = 0.f;
    const float4* x4 = (const float4*)xg;
    const int n4 = CPG * HW / 4;
    for (int i = tid; i < n4; i += 256) {
        float4 v = x4[i];
        s  += v.x + v.y + v.z + v.w;
        ss += v.x*v.x + v.y*v.y + v.z*v.z + v.w*v.w;
    }
    s = warpSum(s); ss = warpSum(ss);
    __shared__ float shs[8], shss[8];
    __shared__ float s_mean, s_rstd;
    const int lane = tid & 31, wid = tid >> 5;
    if (lane == 0) { shs[wid] = s; shss[wid] = ss; }
    __syncthreads();
    if (tid < 32) {
        float a = (lane < 8) ? shs[lane]  : 0.f;
        float c = (lane < 8) ? shss[lane] : 0.f;
        a = warpSum(a); c = warpSum(c);
        if (lane == 0) {
            const float inv_n = 1.f / (float)(CPG * HW);
            float mean = a * inv_n;
            float var  = c * inv_n - mean * mean;
            s_mean = mean;
            s_rstd = rsqrtf(var + EPS);
        }
    }
    __syncthreads();
    const float mean = s_mean, rstd = s_rstd;

    const int cl = tid & 15;
    const int pr = tid >> 4;
    const int c0 = g * CPG;
    const float gm = gamma[c0 + cl] * rstd;
    const float bt = beta[c0 + cl] - mean * gm;

    __shared__ float tile[CPG][257];
    float* tb = t + (long long)b * HW * CH + c0;
    for (int pbase = 0; pbase < HW; pbase += 256) {
#pragma unroll
        for (int c = 0; c < CPG; c++)
            tile[c][tid] = xg[(long long)c * HW + pbase + tid];
        __syncthreads();
#pragma unroll
        for (int pp = 0; pp < 16; pp++) {
            int pl = pp * 16 + pr;
            tb[(long long)(pbase + pl) * CH + cl] = tile[cl][pl] * gm + bt;
        }
        __syncthreads();
    }
}

// ---------------------------------------------------------------------------
// TF32 tensor-core GEMM-NT: C[m][n] = alpha*sum_k A[m][k]*B[n][k] (+bias)(+resid)
// A: MxK row-major, B: NxK row-major, C: MxN row-major.
// 128x128 CTA tile, K-tile 16, 4 warps (2x2), warp tile 64x64.
// Big warp tiles halve smem crossbar traffic per MAC (the measured binder:
// tensor pipe was pinned at ~45% by fragment LDS bytes at 64x32 tiles).
// 4-stage cp.async pipeline (dynamic smem 80KB), prefetch distance 3.
// BIAS: 0 none, 1 per-col (bias[n]), 2 per-row (bias[m]).
// All dims divide tiles exactly in this problem -> no bounds checks.
// ---------------------------------------------------------------------------
template<int BIAS, bool ADD_RESID>
__global__ void __launch_bounds__(128, 2) mma_nt(
    const float* __restrict__ A, const float* __restrict__ Bm,
    float* __restrict__ C, const float* __restrict__ bias,
    const float* __restrict__ resid,
    int M, int N, int K, float alpha,
    long long sA, long long sB, long long sC, long long sR)
{
    extern __shared__ uint32_t smem[];
    uint32_t* As = smem;                          // [STAGES][128][SROW]
    uint32_t* Bs = smem + STAGES * STAGE_U32;     // [STAGES][128][SROW]

    const int z = blockIdx.z;
    A  += z * sA;
    Bm += z * sB;
    C  += z * sC;
    if (ADD_RESID) resid += z * sR;

    const int bm = blockIdx.y * 128;
    const int bn = blockIdx.x * 128;
    const int tid  = threadIdx.x;
    const int lane = tid & 31;
    const int wid  = tid >> 5;        // 0..3
    const int wm = wid >> 1;          // 0..1
    const int wn = wid & 1;           // 0..1
    const int g  = lane >> 2;         // 0..7
    const int t  = lane & 3;          // 0..3

    // global load coords: 4 16B chunks per operand per thread (rows r0+32i)
    const int r0  = tid >> 2;         // 0..31
    const int col = (tid & 3) << 2;   // 0,4,8,12

    const float* Ap = A  + (long long)(bm + r0) * K + col;
    const float* Bp = Bm + (long long)(bn + r0) * K + col;

    // per-stage smem base (row r0); row+32i adds a constant offset
    uint32_t dA[STAGES], dB[STAGES];
#pragma unroll
    for (int s2 = 0; s2 < STAGES; s2++) {
        dA[s2] = (uint32_t)__cvta_generic_to_shared(&As[s2*STAGE_U32 + r0*SROW + col]);
        dB[s2] = (uint32_t)__cvta_generic_to_shared(&Bs[s2*STAGE_U32 + r0*SROW + col]);
    }
    const uint32_t rowHop = 32 * SROW * 4;        // bytes per 32 rows

    float acc[4][8][4];
#pragma unroll
    for (int i = 0; i < 4; i++)
#pragma unroll
        for (int j = 0; j < 8; j++)
#pragma unroll
            for (int e = 0; e < 4; e++) acc[i][j][e] = 0.f;

    const int nt = K >> 4;            // >= 32 for all calls here

    // prologue: issue stages 0..2 (3 groups in flight)
#pragma unroll
    for (int p = 0; p < STAGES - 1; p++) {
        int off = p << 4;
#pragma unroll
        for (int i = 0; i < 4; i++) {
            cp16(dA[p] + i * rowHop, Ap + (long long)i * 32 * K + off);
            cp16(dB[p] + i * rowHop, Bp + (long long)i * 32 * K + off);
        }
        cp_commit();
    }

    for (int kt = 0; kt < nt; kt++) {
        cp_wait<STAGES - 2>();        // stage kt%STAGES has landed
        __syncthreads();              // all warps done with the stage we refill

        {                             // prefetch kt+3 (possibly empty group)
            int pf = kt + STAGES - 1;
            if (pf < nt) {
                int sb = pf & (STAGES - 1);
                int off = pf << 4;
#pragma unroll
                for (int i = 0; i < 4; i++) {
                    cp16(dA[sb] + i * rowHop, Ap + (long long)i * 32 * K + off);
                    cp16(dB[sb] + i * rowHop, Bp + (long long)i * 32 * K + off);
                }
            }
            cp_commit();              // always: keeps group accounting exact
        }

        const uint32_t* Abuf = As + (kt & (STAGES - 1)) * STAGE_U32;
        const uint32_t* Bbuf = Bs + (kt & (STAGES - 1)) * STAGE_U32;
#pragma unroll
        for (int ks = 0; ks < 2; ks++) {
            const int kk = ks * 8;
            uint32_t af[4][4], bf[8][2];
#pragma unroll
            for (int mt = 0; mt < 4; mt++) {
                const uint32_t* p = &Abuf[(wm*64 + mt*16 + g)*SROW + kk + t];
                af[mt][0] = p[0];
                af[mt][1] = p[8 * SROW];
                af[mt][2] = p[4];
                af[mt][3] = p[8 * SROW + 4];
            }
#pragma unroll
            for (int jt = 0; jt < 8; jt++) {
                const uint32_t* p = &Bbuf[(wn*64 + jt*8 + g)*SROW + kk + t];
                bf[jt][0] = p[0];
                bf[jt][1] = p[4];
            }
#pragma unroll
            for (int mt = 0; mt < 4; mt++)
#pragma unroll
                for (int jt = 0; jt < 8; jt++)
                    mma8(acc[mt][jt], af[mt], bf[jt]);
        }
    }

    // Epilogue: float2 stores, coalesced row-major
#pragma unroll
    for (int mt = 0; mt < 4; mt++) {
        const int m0 = bm + wm*64 + mt*16 + g;
        const int m1 = m0 + 8;
        float rb0 = 0.f, rb1 = 0.f;
        if (BIAS == 2) { rb0 = bias[m0]; rb1 = bias[m1]; }
#pragma unroll
        for (int jt = 0; jt < 8; jt++) {
            const int n0 = bn + wn*64 + jt*8 + t*2;
            float2 cb = make_float2(0.f, 0.f);
            if (BIAS == 1) cb = *(const float2*)(bias + n0);
            float2 v0, v1;
            v0.x = acc[mt][jt][0]*alpha; v0.y = acc[mt][jt][1]*alpha;
            v1.x = acc[mt][jt][2]*alpha; v1.y = acc[mt][jt][3]*alpha;
            if (BIAS == 1) { v0.x+=cb.x; v0.y+=cb.y; v1.x+=cb.x; v1.y+=cb.y; }
            if (BIAS == 2) { v0.x+=rb0; v0.y+=rb0; v1.x+=rb1; v1.y+=rb1; }
            if (ADD_RESID) {
                float2 r0v = *(const float2*)(resid + (long long)m0 * N + n0);
                float2 r1v = *(const float2*)(resid + (long long)m1 * N + n0);
                v0.x+=r0v.x; v0.y+=r0v.y; v1.x+=r1v.x; v1.y+=r1v.y;
            }
            *(float2*)(C + (long long)m0 * N + n0) = v0;
            *(float2*)(C + (long long)m1 * N + n0) = v1;
        }
    }
}

// ---------------------------------------------------------------------------
// Row softmax over 4096 entries; row lives in registers between passes.
// ---------------------------------------------------------------------------
__global__ void __launch_bounds__(256) softmax_kernel(float* __restrict__ s)
{
    float4* row = (float4*)(s + (long long)blockIdx.x * HW);
    const int tid = threadIdx.x;
    const int lane = tid & 31, wid = tid >> 5;
    __shared__ float sh[8];
    __shared__ float s_bcast;

    float4 v[4];
    float m = -INFINITY;
#pragma unroll
    for (int u = 0; u < 4; u++) {
        v[u] = row[tid + u * 256];
        m = fmaxf(m, fmaxf(fmaxf(v[u].x, v[u].y), fmaxf(v[u].z, v[u].w)));
    }
    m = warpMax(m);
    if (lane == 0) sh[wid] = m;
    __syncthreads();
    if (tid < 32) {
        float a = (lane < 8) ? sh[lane] : -INFINITY;
        a = warpMax(a);
        if (lane == 0) s_bcast = a;
    }
    __syncthreads();
    m = s_bcast;

    float sum = 0.f;
#pragma unroll
    for (int u = 0; u < 4; u++) {
        v[u].x = __expf(v[u].x - m); v[u].y = __expf(v[u].y - m);
        v[u].z = __expf(v[u].z - m); v[u].w = __expf(v[u].w - m);
        sum += v[u].x + v[u].y + v[u].z + v[u].w;
    }
    sum = warpSum(sum);
    __syncthreads();
    if (lane == 0) sh[wid] = sum;
    __syncthreads();
    if (tid < 32) {
        float a = (lane < 8) ? sh[lane] : 0.f;
        a = warpSum(a);
        if (lane == 0) s_bcast = a;
    }
    __syncthreads();
    const float inv = 1.f / s_bcast;
#pragma unroll
    for (int u = 0; u < 4; u++) {
        v[u].x *= inv; v[u].y *= inv; v[u].z *= inv; v[u].w *= inv;
        row[tid + u * 256] = v[u];
    }
}

// ---------------------------------------------------------------------------
// Launch. All GEMMs are NT on tensor cores; transposed outputs realized by
// operand swap (compute W * X^T) instead of scattered epilogues.
// ---------------------------------------------------------------------------
extern "C" void kernel_launch(void* const* d_in, const int* in_sizes, int n_in,
                              void* d_out, int out_size)
{
    const float* x    = (const float*)d_in[0];
    const float* gn_w = (const float*)d_in[1];
    const float* gn_b = (const float*)d_in[2];
    const float* wq   = (const float*)d_in[3];
    const float* bq   = (const float*)d_in[4];
    const float* wk   = (const float*)d_in[5];
    const float* bk   = (const float*)d_in[6];
    const float* wv   = (const float*)d_in[7];
    const float* bv   = (const float*)d_in[8];
    const float* wo   = (const float*)d_in[9];
    const float* bo   = (const float*)d_in[10];
    float* out = (float*)d_out;

    float *t, *q, *k, *vt, *s;
    cudaGetSymbolAddress((void**)&t,  g_t);
    cudaGetSymbolAddress((void**)&q,  g_q);
    cudaGetSymbolAddress((void**)&k,  g_k);
    cudaGetSymbolAddress((void**)&vt, g_vt);
    cudaGetSymbolAddress((void**)&s,  g_s);
    float* o = t;   // tokens dead after V projection; reuse

    const long long sTok = (long long)HW * CH;
    const long long sSc  = (long long)HW * HW;

    // allow 80KB dynamic smem on every instantiation (idempotent, capture-safe)
    cudaFuncSetAttribute(mma_nt<1, false>,
        cudaFuncAttributeMaxDynamicSharedMemorySize, SMEM_BYTES);
    cudaFuncSetAttribute(mma_nt<2, false>,
        cudaFuncAttributeMaxDynamicSharedMemorySize, SMEM_BYTES);
    cudaFuncSetAttribute(mma_nt<0, false>,
        cudaFuncAttributeMaxDynamicSharedMemorySize, SMEM_BYTES);
    cudaFuncSetAttribute(mma_nt<2, true>,
        cudaFuncAttributeMaxDynamicSharedMemorySize, SMEM_BYTES);

    // 1) GroupNorm -> tokens (B,HW,C)
    groupnorm_kernel<<<BATCH * GROUPS, 256>>>(x, gn_w, gn_b, t);

    // 2) Q = t @ Wq^T + bq ; K likewise.  M=HW, N=CH, K=CH, col bias.
    dim3 gQK(CH / 128, HW / 128, BATCH);
    mma_nt<1, false><<<gQK, 128, SMEM_BYTES>>>(t, wq, q, bq, nullptr,
        HW, CH, CH, 1.f, sTok, 0, sTok, 0);
    mma_nt<1, false><<<gQK, 128, SMEM_BYTES>>>(t, wk, k, bk, nullptr,
        HW, CH, CH, 1.f, sTok, 0, sTok, 0);

    // 3) V^T = Wv @ t^T + bv (per-row bias). M=CH, N=HW, K=CH.
    dim3 gVT(HW / 128, CH / 128, BATCH);
    mma_nt<2, false><<<gVT, 128, SMEM_BYTES>>>(wv, t, vt, bv, nullptr,
        CH, HW, CH, 1.f, 0, sTok, sTok, 0);

    // 4) scores = scale * Q @ K^T. M=N=HW, K=CH.
    dim3 gSc(HW / 128, HW / 128, BATCH);
    mma_nt<0, false><<<gSc, 128, SMEM_BYTES>>>(q, k, s, nullptr, nullptr,
        HW, HW, CH, SCALE, sTok, sTok, sSc, 0);

    // 5) softmax rows
    softmax_kernel<<<BATCH * HW, 256>>>(s);

    // 6) O = P @ V  (B = vt rows are channels: NT). M=HW, N=CH, K=HW.
    dim3 gPV(CH / 128, HW / 128, BATCH);
    mma_nt<0, false><<<gPV, 128, SMEM_BYTES>>>(s, vt, o, nullptr, nullptr,
        HW, CH, HW, 1.f, sSc, sTok, sTok, 0);

    // 7) out^T = Wo @ O^T + bo + x, directly in (B,C,HW). M=CH, N=HW, K=CH.
    dim3 gO(HW / 128, CH / 128, BATCH);
    mma_nt<2, true><<<gO, 128, SMEM_BYTES>>>(wo, o, out, bo, x,
        CH, HW, CH, 1.f, 0, sTok, sTok, sTok);
}

// round 11
// speedup vs baseline: 1.9216x; 1.8553x over previous
#include <cuda_runtime.h>
#include <cuda_fp16.h>
#include <math.h>
#include <stdint.h>

// Problem constants
#define BATCH 8
#define CH    512
#define HW    4096
#define GROUPS 32
#define CPG   16
#define EPS   1e-5f
#define SCALE 0.04419417382415922f   // 512^-0.5

#define STAGES 4
#define KTILE  32                     // half elements per K-tile (64B/row)
#define SROW   20                     // row stride in u32 (40 halves, padded)
#define STAGE_U32 (128 * SROW)        // u32 per operand per stage
#define SMEM_BYTES (STAGES * STAGE_U32 * 4 * 2)   // 81920 B

// ---------------------------------------------------------------------------
// Scratch (device globals; allocation in kernel_launch is forbidden)
// ---------------------------------------------------------------------------
__device__ __half g_wh [4 * CH * CH];                    // wq,wk,wv,wo in half
__device__ __half g_th [(long long)BATCH * HW * CH];     // normalized tokens
__device__ __half g_qh [(long long)BATCH * HW * CH];
__device__ __half g_kh [(long long)BATCH * HW * CH];
__device__ __half g_vth[(long long)BATCH * CH * HW];     // V^T (B,C,HW)
__device__ __half g_oh [(long long)BATCH * HW * CH];     // attn out (half)
__device__ __half g_ph [(long long)BATCH * HW * HW];     // probs (half) ~268MB
__device__ float  g_s  [(long long)BATCH * HW * HW];     // scores fp32 ~537MB

// ---------------------------------------------------------------------------
__device__ __forceinline__ float warpSum(float v) {
#pragma unroll
    for (int o = 16; o > 0; o >>= 1) v += __shfl_xor_sync(0xffffffffu, v, o);
    return v;
}
__device__ __forceinline__ float warpMax(float v) {
#pragma unroll
    for (int o = 16; o > 0; o >>= 1) v = fmaxf(v, __shfl_xor_sync(0xffffffffu, v, o));
    return v;
}
// m16n8k16 fp16 MMA, fp32 accumulate
__device__ __forceinline__ void mma16(float* c, const uint32_t* a, const uint32_t* b) {
    asm volatile(
        "mma.sync.aligned.m16n8k16.row.col.f32.f16.f16.f32 "
        "{%0,%1,%2,%3},{%4,%5,%6,%7},{%8,%9},{%0,%1,%2,%3};\n"
        : "+f"(c[0]), "+f"(c[1]), "+f"(c[2]), "+f"(c[3])
        : "r"(a[0]), "r"(a[1]), "r"(a[2]), "r"(a[3]), "r"(b[0]), "r"(b[1]));
}
__device__ __forceinline__ void cp16(uint32_t smem_addr, const void* gptr) {
    asm volatile("cp.async.cg.shared.global [%0], [%1], 16;\n"
                 :: "r"(smem_addr), "l"(gptr));
}
__device__ __forceinline__ void cp_commit() {
    asm volatile("cp.async.commit_group;\n" ::: "memory");
}
template<int N>
__device__ __forceinline__ void cp_wait() {
    asm volatile("cp.async.wait_group %0;\n" :: "n"(N) : "memory");
}

// ---------------------------------------------------------------------------
// Convert the four 512x512 weight matrices to half (one-time, ~2MB)
// ---------------------------------------------------------------------------
__global__ void __launch_bounds__(256) cvt_weights_kernel(
    const float* __restrict__ wq, const float* __restrict__ wk,
    const float* __restrict__ wv, const float* __restrict__ wo,
    __half* __restrict__ dst)
{
    const float* srcs[4] = {wq, wk, wv, wo};
    const float* s = srcs[blockIdx.y];
    __half* d = dst + blockIdx.y * (CH * CH);
    int i = (blockIdx.x * 256 + threadIdx.x) * 4;
    float4 v = *(const float4*)(s + i);
    __half2* d2 = (__half2*)(d + i);
    d2[0] = __floats2half2_rn(v.x, v.y);
    d2[1] = __floats2half2_rn(v.z, v.w);
}

// ---------------------------------------------------------------------------
// GroupNorm + transpose to token-major (B,HW,C), half output
// ---------------------------------------------------------------------------
__global__ void __launch_bounds__(256) groupnorm_kernel(
    const float* __restrict__ x, const float* __restrict__ gamma,
    const float* __restrict__ beta, __half* __restrict__ t)
{
    const int bg = blockIdx.x;
    const int b = bg >> 5, g = bg & 31;
    const int tid = threadIdx.x;
    const float* xg = x + ((long long)b * CH + (long long)g * CPG) * HW;

    float s = 0.f, ss = 0.f;
    const float4* x4 = (const float4*)xg;
    const int n4 = CPG * HW / 4;
    for (int i = tid; i < n4; i += 256) {
        float4 v = x4[i];
        s  += v.x + v.y + v.z + v.w;
        ss += v.x*v.x + v.y*v.y + v.z*v.z + v.w*v.w;
    }
    s = warpSum(s); ss = warpSum(ss);
    __shared__ float shs[8], shss[8];
    __shared__ float s_mean, s_rstd;
    const int lane = tid & 31, wid = tid >> 5;
    if (lane == 0) { shs[wid] = s; shss[wid] = ss; }
    __syncthreads();
    if (tid < 32) {
        float a = (lane < 8) ? shs[lane]  : 0.f;
        float c = (lane < 8) ? shss[lane] : 0.f;
        a = warpSum(a); c = warpSum(c);
        if (lane == 0) {
            const float inv_n = 1.f / (float)(CPG * HW);
            float mean = a * inv_n;
            float var  = c * inv_n - mean * mean;
            s_mean = mean;
            s_rstd = rsqrtf(var + EPS);
        }
    }
    __syncthreads();
    const float mean = s_mean, rstd = s_rstd;

    const int cl = tid & 15;
    const int pr = tid >> 4;
    const int c0 = g * CPG;
    const float gm = gamma[c0 + cl] * rstd;
    const float bt = beta[c0 + cl] - mean * gm;

    __shared__ float tile[CPG][257];
    __half* tb = t + (long long)b * HW * CH + c0;
    for (int pbase = 0; pbase < HW; pbase += 256) {
#pragma unroll
        for (int c = 0; c < CPG; c++)
            tile[c][tid] = xg[(long long)c * HW + pbase + tid];
        __syncthreads();
#pragma unroll
        for (int pp = 0; pp < 16; pp++) {
            int pl = pp * 16 + pr;
            tb[(long long)(pbase + pl) * CH + cl] =
                __float2half_rn(tile[cl][pl] * gm + bt);
        }
        __syncthreads();
    }
}

// ---------------------------------------------------------------------------
// FP16 tensor-core GEMM-NT: C[m][n] = alpha*sum_k A[m][k]*B[n][k] (+bias)(+resid)
// A: MxK half row-major, B: NxK half row-major. C fp32 or half row-major.
// 128x128 CTA tile, K-tile 32, 4 warps (2x2), warp tile 64x64.
// mma.sync.m16n8k16.f16 (fp32 accum). 4-stage cp.async pipeline.
// Fragment smem addressing identical (in u32 units) to the proven tf32 kernel.
// BIAS: 0 none, 1 per-col (bias[n]), 2 per-row (bias[m]).
// All dims divide tiles exactly in this problem -> no bounds checks.
// ---------------------------------------------------------------------------
template<int BIAS, bool ADD_RESID, bool OUT_HALF>
__global__ void __launch_bounds__(128, 2) mma_nt(
    const __half* __restrict__ A, const __half* __restrict__ Bm,
    void* __restrict__ Cv, const float* __restrict__ bias,
    const float* __restrict__ resid,
    int M, int N, int K, float alpha,
    long long sA, long long sB, long long sC, long long sR)
{
    extern __shared__ uint32_t smem[];
    uint32_t* As = smem;                          // [STAGES][128][SROW] u32
    uint32_t* Bs = smem + STAGES * STAGE_U32;

    const int z = blockIdx.z;
    A  += z * sA;
    Bm += z * sB;
    float*  Cf = (float*) Cv + (OUT_HALF ? 0 : z * sC);
    __half* Ch = (__half*)Cv + (OUT_HALF ? z * sC : 0);
    if (ADD_RESID) resid += z * sR;

    const int bm = blockIdx.y * 128;
    const int bn = blockIdx.x * 128;
    const int tid  = threadIdx.x;
    const int lane = tid & 31;
    const int wid  = tid >> 5;        // 0..3
    const int wm = wid >> 1;          // 0..1
    const int wn = wid & 1;           // 0..1
    const int g  = lane >> 2;         // 0..7
    const int t  = lane & 3;          // 0..3

    // global load coords: 4 16B chunks per operand per thread (rows r0+32i)
    const int r0   = tid >> 2;        // 0..31
    const int colh = (tid & 3) << 3;  // half offset: 0,8,16,24
    const int colu = (tid & 3) << 2;  // u32 offset in smem row

    const __half* Ap = A  + (long long)(bm + r0) * K + colh;
    const __half* Bp = Bm + (long long)(bn + r0) * K + colh;

    uint32_t dA[STAGES], dB[STAGES];
#pragma unroll
    for (int s2 = 0; s2 < STAGES; s2++) {
        dA[s2] = (uint32_t)__cvta_generic_to_shared(&As[s2*STAGE_U32 + r0*SROW + colu]);
        dB[s2] = (uint32_t)__cvta_generic_to_shared(&Bs[s2*STAGE_U32 + r0*SROW + colu]);
    }
    const uint32_t rowHop = 32 * SROW * 4;        // bytes per 32 rows

    float acc[4][8][4];
#pragma unroll
    for (int i = 0; i < 4; i++)
#pragma unroll
        for (int j = 0; j < 8; j++)
#pragma unroll
            for (int e = 0; e < 4; e++) acc[i][j][e] = 0.f;

    const int nt = K / KTILE;         // >= 16 for all calls here

    // prologue: issue stages 0..2
#pragma unroll
    for (int p = 0; p < STAGES - 1; p++) {
        int off = p * KTILE;
#pragma unroll
        for (int i = 0; i < 4; i++) {
            cp16(dA[p] + i * rowHop, Ap + (long long)i * 32 * K + off);
            cp16(dB[p] + i * rowHop, Bp + (long long)i * 32 * K + off);
        }
        cp_commit();
    }

    for (int kt = 0; kt < nt; kt++) {
        cp_wait<STAGES - 2>();
        __syncthreads();

        {   // prefetch kt+3 (possibly empty group keeps accounting exact)
            int pf = kt + STAGES - 1;
            if (pf < nt) {
                int sb = pf & (STAGES - 1);
                int off = pf * KTILE;
#pragma unroll
                for (int i = 0; i < 4; i++) {
                    cp16(dA[sb] + i * rowHop, Ap + (long long)i * 32 * K + off);
                    cp16(dB[sb] + i * rowHop, Bp + (long long)i * 32 * K + off);
                }
            }
            cp_commit();
        }

        const uint32_t* Abuf = As + (kt & (STAGES - 1)) * STAGE_U32;
        const uint32_t* Bbuf = Bs + (kt & (STAGES - 1)) * STAGE_U32;
#pragma unroll
        for (int ks = 0; ks < 2; ks++) {
            const int kk = ks * 8;    // u32 offset: 16 halves per ks
            uint32_t af[4][4], bf[8][2];
#pragma unroll
            for (int mt = 0; mt < 4; mt++) {
                const uint32_t* p = &Abuf[(wm*64 + mt*16 + g)*SROW + kk + t];
                af[mt][0] = p[0];            // row g,   k 2t..2t+1
                af[mt][1] = p[8 * SROW];     // row g+8, k 2t..2t+1
                af[mt][2] = p[4];            // row g,   k 8+2t..
                af[mt][3] = p[8 * SROW + 4]; // row g+8, k 8+2t..
            }
#pragma unroll
            for (int jt = 0; jt < 8; jt++) {
                const uint32_t* p = &Bbuf[(wn*64 + jt*8 + g)*SROW + kk + t];
                bf[jt][0] = p[0];
                bf[jt][1] = p[4];
            }
#pragma unroll
            for (int mt = 0; mt < 4; mt++)
#pragma unroll
                for (int jt = 0; jt < 8; jt++)
                    mma16(acc[mt][jt], af[mt], bf[jt]);
        }
    }

    // Epilogue
#pragma unroll
    for (int mt = 0; mt < 4; mt++) {
        const int m0 = bm + wm*64 + mt*16 + g;
        const int m1 = m0 + 8;
        float rb0 = 0.f, rb1 = 0.f;
        if (BIAS == 2) { rb0 = bias[m0]; rb1 = bias[m1]; }
#pragma unroll
        for (int jt = 0; jt < 8; jt++) {
            const int n0 = bn + wn*64 + jt*8 + t*2;
            float2 cb = make_float2(0.f, 0.f);
            if (BIAS == 1) cb = *(const float2*)(bias + n0);
            float2 v0, v1;
            v0.x = acc[mt][jt][0]*alpha; v0.y = acc[mt][jt][1]*alpha;
            v1.x = acc[mt][jt][2]*alpha; v1.y = acc[mt][jt][3]*alpha;
            if (BIAS == 1) { v0.x+=cb.x; v0.y+=cb.y; v1.x+=cb.x; v1.y+=cb.y; }
            if (BIAS == 2) { v0.x+=rb0; v0.y+=rb0; v1.x+=rb1; v1.y+=rb1; }
            if (ADD_RESID) {
                float2 r0v = *(const float2*)(resid + (long long)m0 * N + n0);
                float2 r1v = *(const float2*)(resid + (long long)m1 * N + n0);
                v0.x+=r0v.x; v0.y+=r0v.y; v1.x+=r1v.x; v1.y+=r1v.y;
            }
            if (OUT_HALF) {
                *(__half2*)(Ch + (long long)m0 * N + n0) = __floats2half2_rn(v0.x, v0.y);
                *(__half2*)(Ch + (long long)m1 * N + n0) = __floats2half2_rn(v1.x, v1.y);
            } else {
                *(float2*)(Cf + (long long)m0 * N + n0) = v0;
                *(float2*)(Cf + (long long)m1 * N + n0) = v1;
            }
        }
    }
}

// ---------------------------------------------------------------------------
// Row softmax over 4096 fp32 scores -> half probabilities (separate buffer).
// Row lives in registers between passes.
// ---------------------------------------------------------------------------
__global__ void __launch_bounds__(256) softmax_kernel(
    const float* __restrict__ s, __half* __restrict__ p)
{
    const float4* row = (const float4*)(s + (long long)blockIdx.x * HW);
    __half2* prow = (__half2*)(p + (long long)blockIdx.x * HW);
    const int tid = threadIdx.x;
    const int lane = tid & 31, wid = tid >> 5;
    __shared__ float sh[8];
    __shared__ float s_bcast;

    float4 v[4];
    float m = -INFINITY;
#pragma unroll
    for (int u = 0; u < 4; u++) {
        v[u] = row[tid + u * 256];
        m = fmaxf(m, fmaxf(fmaxf(v[u].x, v[u].y), fmaxf(v[u].z, v[u].w)));
    }
    m = warpMax(m);
    if (lane == 0) sh[wid] = m;
    __syncthreads();
    if (tid < 32) {
        float a = (lane < 8) ? sh[lane] : -INFINITY;
        a = warpMax(a);
        if (lane == 0) s_bcast = a;
    }
    __syncthreads();
    m = s_bcast;

    float sum = 0.f;
#pragma unroll
    for (int u = 0; u < 4; u++) {
        v[u].x = __expf(v[u].x - m); v[u].y = __expf(v[u].y - m);
        v[u].z = __expf(v[u].z - m); v[u].w = __expf(v[u].w - m);
        sum += v[u].x + v[u].y + v[u].z + v[u].w;
    }
    sum = warpSum(sum);
    __syncthreads();
    if (lane == 0) sh[wid] = sum;
    __syncthreads();
    if (tid < 32) {
        float a = (lane < 8) ? sh[lane] : 0.f;
        a = warpSum(a);
        if (lane == 0) s_bcast = a;
    }
    __syncthreads();
    const float inv = 1.f / s_bcast;
#pragma unroll
    for (int u = 0; u < 4; u++) {
        int i = tid + u * 256;
        prow[2*i  ] = __floats2half2_rn(v[u].x * inv, v[u].y * inv);
        prow[2*i+1] = __floats2half2_rn(v[u].z * inv, v[u].w * inv);
    }
}

// ---------------------------------------------------------------------------
// Launch
// ---------------------------------------------------------------------------
extern "C" void kernel_launch(void* const* d_in, const int* in_sizes, int n_in,
                              void* d_out, int out_size)
{
    const float* x    = (const float*)d_in[0];
    const float* gn_w = (const float*)d_in[1];
    const float* gn_b = (const float*)d_in[2];
    const float* wq   = (const float*)d_in[3];
    const float* bq   = (const float*)d_in[4];
    const float* wk   = (const float*)d_in[5];
    const float* bk   = (const float*)d_in[6];
    const float* wv   = (const float*)d_in[7];
    const float* bv   = (const float*)d_in[8];
    const float* wo   = (const float*)d_in[9];
    const float* bo   = (const float*)d_in[10];
    float* out = (float*)d_out;

    __half *wh, *th, *qh, *kh, *vth, *oh, *ph;
    float* s;
    cudaGetSymbolAddress((void**)&wh,  g_wh);
    cudaGetSymbolAddress((void**)&th,  g_th);
    cudaGetSymbolAddress((void**)&qh,  g_qh);
    cudaGetSymbolAddress((void**)&kh,  g_kh);
    cudaGetSymbolAddress((void**)&vth, g_vth);
    cudaGetSymbolAddress((void**)&oh,  g_oh);
    cudaGetSymbolAddress((void**)&ph,  g_ph);
    cudaGetSymbolAddress((void**)&s,   g_s);

    const __half* wqh = wh;
    const __half* wkh = wh + 1 * CH * CH;
    const __half* wvh = wh + 2 * CH * CH;
    const __half* woh = wh + 3 * CH * CH;

    const long long sTok = (long long)HW * CH;
    const long long sSc  = (long long)HW * HW;

    cudaFuncSetAttribute(mma_nt<1, false, true>,
        cudaFuncAttributeMaxDynamicSharedMemorySize, SMEM_BYTES);
    cudaFuncSetAttribute(mma_nt<2, false, true>,
        cudaFuncAttributeMaxDynamicSharedMemorySize, SMEM_BYTES);
    cudaFuncSetAttribute(mma_nt<0, false, false>,
        cudaFuncAttributeMaxDynamicSharedMemorySize, SMEM_BYTES);
    cudaFuncSetAttribute(mma_nt<0, false, true>,
        cudaFuncAttributeMaxDynamicSharedMemorySize, SMEM_BYTES);
    cudaFuncSetAttribute(mma_nt<2, true, false>,
        cudaFuncAttributeMaxDynamicSharedMemorySize, SMEM_BYTES);

    // 0) Weights -> half
    cvt_weights_kernel<<<dim3(256, 4), 256>>>(wq, wk, wv, wo, wh);

    // 1) GroupNorm -> tokens (B,HW,C) half
    groupnorm_kernel<<<BATCH * GROUPS, 256>>>(x, gn_w, gn_b, th);

    // 2) Q = t @ Wq^T + bq ; K likewise. M=HW, N=CH, K=CH, col bias, half out.
    dim3 gQK(CH / 128, HW / 128, BATCH);
    mma_nt<1, false, true><<<gQK, 128, SMEM_BYTES>>>(th, wqh, qh, bq, nullptr,
        HW, CH, CH, 1.f, sTok, 0, sTok, 0);
    mma_nt<1, false, true><<<gQK, 128, SMEM_BYTES>>>(th, wkh, kh, bk, nullptr,
        HW, CH, CH, 1.f, sTok, 0, sTok, 0);

    // 3) V^T = Wv @ t^T + bv (row bias). M=CH, N=HW, K=CH, half out.
    dim3 gVT(HW / 128, CH / 128, BATCH);
    mma_nt<2, false, true><<<gVT, 128, SMEM_BYTES>>>(wvh, th, vth, bv, nullptr,
        CH, HW, CH, 1.f, 0, sTok, sTok, 0);

    // 4) scores = scale * Q @ K^T. M=N=HW, K=CH, fp32 out.
    dim3 gSc(HW / 128, HW / 128, BATCH);
    mma_nt<0, false, false><<<gSc, 128, SMEM_BYTES>>>(qh, kh, s, nullptr, nullptr,
        HW, HW, CH, SCALE, sTok, sTok, sSc, 0);

    // 5) softmax rows: fp32 scores -> half probs
    softmax_kernel<<<BATCH * HW, 256>>>(s, ph);

    // 6) O = P @ V. M=HW, N=CH, K=HW, half out.
    dim3 gPV(CH / 128, HW / 128, BATCH);
    mma_nt<0, false, true><<<gPV, 128, SMEM_BYTES>>>(ph, vth, oh, nullptr, nullptr,
        HW, CH, HW, 1.f, sSc, sTok, sTok, 0);

    // 7) out^T = Wo @ O^T + bo + x, fp32, directly in (B,C,HW). M=CH, N=HW, K=CH.
    dim3 gO(HW / 128, CH / 128, BATCH);
    mma_nt<2, true, false><<<gO, 128, SMEM_BYTES>>>(woh, oh, out, bo, x,
        CH, HW, CH, 1.f, 0, sTok, sTok, sTok);
}